// round 15
// baseline (speedup 1.0000x reference)
#include <cuda_runtime.h>
#include <math.h>
#include <stdint.h>

#define NR 4096
#define DD 1024
#define DI 4096
#define DL 64
#define KSPLIT 8

// scratch
__device__ float g_h[(size_t)4096 * 4096];           // 64MB hidden activations (tf32-rounded)
__device__ float g_part[(size_t)KSPLIT * 4096 * 64]; // 8MB split-K partials
__device__ float g_hidc[(size_t)NR * DD];            // hidden input, tf32-rounded
__device__ float g_wc1[(size_t)DD * DI];             // enc_w1, tf32-rounded
__device__ float g_dw1[(size_t)DL * DI];             // dec_w1, tf32-rounded
__device__ float g_dw2[(size_t)DI * DD];             // dec_w2, tf32-rounded
__device__ float g_latc[(size_t)NR * DL];            // latent, tf32-rounded
__device__ float g_x2[4096];
__device__ float g_y2[4096];
__device__ double g_acc[3];

__device__ __forceinline__ float gelu_f(float x) {
    return 0.5f * x * (1.0f + erff(x * 0.70710678118654752440f));
}

__device__ __forceinline__ unsigned f2tf32(float x) {
    unsigned u;
    asm("cvt.rna.tf32.f32 %0, %1;" : "=r"(u) : "f"(x));
    return u;
}
__device__ __forceinline__ float tf32r(float x) { return __uint_as_float(f2tf32(x)); }

__device__ __forceinline__ void mma_tf32(float* d, const unsigned* a, const unsigned* b) {
    asm volatile(
        "mma.sync.aligned.m16n8k8.row.col.f32.tf32.tf32.f32 "
        "{%0,%1,%2,%3}, {%4,%5,%6,%7}, {%8,%9}, {%0,%1,%2,%3};\n"
        : "+f"(d[0]), "+f"(d[1]), "+f"(d[2]), "+f"(d[3])
        : "r"(a[0]), "r"(a[1]), "r"(a[2]), "r"(a[3]), "r"(b[0]), "r"(b[1]));
}

__device__ __forceinline__ void cp16(float* dst_smem, const float* src) {
    unsigned d = (unsigned)__cvta_generic_to_shared(dst_smem);
    asm volatile("cp.async.cg.shared.global [%0], [%1], 16;\n" :: "r"(d), "l"(src));
}

// elementwise tf32-round copy (float4 vectorized); n multiple of 4
__global__ __launch_bounds__(256) void cvt_tf32_k(
    const float* __restrict__ in, float* __restrict__ out, int n4)
{
    int i = blockIdx.x * 256 + threadIdx.x;
    if (i < n4) {
        float4 v = ((const float4*)in)[i];
        float4 w;
        w.x = tf32r(v.x); w.y = tf32r(v.y);
        w.z = tf32r(v.z); w.w = tf32r(v.w);
        ((float4*)out)[i] = w;
    }
}

// smem layout constants for the pipelined GEMM
#define AS_STRIDE 36
#define BS_STRIDE 136
#define AS_ELEMS (128 * AS_STRIDE)   // per stage
#define BS_ELEMS (32 * BS_STRIDE)    // per stage
#define NSTAGES 3
#define GEMM_SMEM_BYTES (NSTAGES * (AS_ELEMS + BS_ELEMS) * 4)

// ---------------------------------------------------------------------------
// TF32 tensor-core GEMM, 3-stage cp.async pipeline, 4 warps x (64x64) tiles.
// Inputs MUST already be tf32-rounded fp32; mainloop is pure LDS + MMA.
//   C[M,N] = A[M,K] @ B[K,N] + bias; GELU / tf32-rounded output optional.
// BM=128 BN=128 BK=32, 128 threads (4 warps, 2m x 2n).
// ---------------------------------------------------------------------------
template <bool GELU, bool CVT_OUT>
__global__ __launch_bounds__(128, 2) void gemm_tc(
    const float* __restrict__ A, const float* __restrict__ B,
    const float* __restrict__ bias, float* __restrict__ C,
    int M, int N, int K)
{
    extern __shared__ float smem[];
    float* Asm = smem;
    float* Bsm = smem + NSTAGES * AS_ELEMS;

    const int tid  = threadIdx.x;
    const int warp = tid >> 5, lane = tid & 31;
    const int gid  = lane >> 2, tig = lane & 3;
    const int wm   = (warp & 1) * 64;
    const int wn   = (warp >> 1) * 64;
    const int bm   = blockIdx.y * 128;
    const int bn   = blockIdx.x * 128;

    auto load_stage = [&](int k0, int s) {
        float* a = Asm + s * AS_ELEMS;
        float* b = Bsm + s * BS_ELEMS;
#pragma unroll
        for (int it = 0; it < 8; it++) {
            int id = tid + 128 * it;
            int r = id >> 3, c = (id & 7) << 2;
            cp16(a + r * AS_STRIDE + c, A + (size_t)(bm + r) * K + k0 + c);
        }
#pragma unroll
        for (int it = 0; it < 8; it++) {
            int id = tid + 128 * it;
            int r = id >> 5, c = (id & 31) << 2;
            cp16(b + r * BS_STRIDE + c, B + (size_t)(k0 + r) * N + bn + c);
        }
        asm volatile("cp.async.commit_group;\n");
    };

    float d[4][8][4];
#pragma unroll
    for (int i = 0; i < 4; i++)
#pragma unroll
        for (int j = 0; j < 8; j++)
#pragma unroll
            for (int r = 0; r < 4; r++) d[i][j][r] = 0.0f;

    const int T = K >> 5;
    load_stage(0, 0);
    if (T > 1) load_stage(32, 1);

    for (int i = 0; i < T; i++) {
        if (i + 1 < T) {
            asm volatile("cp.async.wait_group 1;\n");
        } else {
            asm volatile("cp.async.wait_group 0;\n");
        }
        __syncthreads();

        const float* a = Asm + (i % NSTAGES) * AS_ELEMS;
        const float* b = Bsm + (i % NSTAGES) * BS_ELEMS;

#pragma unroll
        for (int ks = 0; ks < 4; ks++) {
            const int k8 = ks * 8;
            unsigned af[4][4], bf[8][2];
#pragma unroll
            for (int ii = 0; ii < 4; ii++) {
                int m = wm + 16 * ii + gid;
                af[ii][0] = __float_as_uint(a[m * AS_STRIDE + k8 + tig]);
                af[ii][1] = __float_as_uint(a[(m + 8) * AS_STRIDE + k8 + tig]);
                af[ii][2] = __float_as_uint(a[m * AS_STRIDE + k8 + tig + 4]);
                af[ii][3] = __float_as_uint(a[(m + 8) * AS_STRIDE + k8 + tig + 4]);
            }
#pragma unroll
            for (int j = 0; j < 8; j++) {
                int n = wn + 8 * j + gid;
                bf[j][0] = __float_as_uint(b[(k8 + tig) * BS_STRIDE + n]);
                bf[j][1] = __float_as_uint(b[(k8 + tig + 4) * BS_STRIDE + n]);
            }
#pragma unroll
            for (int ii = 0; ii < 4; ii++)
#pragma unroll
                for (int j = 0; j < 8; j++)
                    mma_tf32(d[ii][j], af[ii], bf[j]);
        }

        if (i + 2 < T) load_stage((i + 2) * 32, (i + 2) % NSTAGES);
    }

#pragma unroll
    for (int i = 0; i < 4; i++) {
        int row = bm + wm + 16 * i + gid;
#pragma unroll
        for (int j = 0; j < 8; j++) {
            int col = bn + wn + 8 * j + 2 * tig;
            float bx = bias[col], by = bias[col + 1];
            float r0 = d[i][j][0] + bx, r1 = d[i][j][1] + by;
            float r2 = d[i][j][2] + bx, r3 = d[i][j][3] + by;
            if (GELU) {
                r0 = gelu_f(r0); r1 = gelu_f(r1);
                r2 = gelu_f(r2); r3 = gelu_f(r3);
            }
            if (CVT_OUT) {
                r0 = tf32r(r0); r1 = tf32r(r1);
                r2 = tf32r(r2); r3 = tf32r(r3);
            }
            *(float2*)(C + (size_t)row * N + col)       = make_float2(r0, r1);
            *(float2*)(C + (size_t)(row + 8) * N + col) = make_float2(r2, r3);
        }
    }
}

// ---------------------------------------------------------------------------
// GEMM2 split-K (tf32): part[ks][4096,64] = A[:,ks*512:+512] @ B-slice
// ---------------------------------------------------------------------------
__global__ __launch_bounds__(256, 2) void gemm2_tc(
    const float* __restrict__ A, const float* __restrict__ B,
    float* __restrict__ part)
{
    __shared__ float As[128][36];
    __shared__ float Bs[32][72];

    const int tid  = threadIdx.x;
    const int warp = tid >> 5, lane = tid & 31;
    const int gid  = lane >> 2, tig = lane & 3;
    const int wm   = (warp & 3) * 32;
    const int wn   = (warp >> 2) * 32;
    const int bm   = blockIdx.y * 128;
    const int kbeg = blockIdx.x * (DI / KSPLIT);

    float d[2][4][4];
#pragma unroll
    for (int i = 0; i < 2; i++)
#pragma unroll
        for (int j = 0; j < 4; j++)
#pragma unroll
            for (int r = 0; r < 4; r++) d[i][j][r] = 0.0f;

    for (int kk = 0; kk < DI / KSPLIT; kk += 32) {
        const int k0 = kbeg + kk;
#pragma unroll
        for (int it = 0; it < 4; it++) {
            int id = tid + 256 * it;
            int r = id >> 3, c = (id & 7) << 2;
            *(float4*)&As[r][c] =
                *(const float4*)(A + (size_t)(bm + r) * DI + k0 + c);
        }
#pragma unroll
        for (int it = 0; it < 2; it++) {
            int id = tid + 256 * it;
            int r = id >> 4, c = (id & 15) << 2;
            float4 v = *(const float4*)(B + (size_t)(k0 + r) * DL + c);
            float4 w;
            w.x = tf32r(v.x); w.y = tf32r(v.y);
            w.z = tf32r(v.z); w.w = tf32r(v.w);
            *(float4*)&Bs[r][c] = w;
        }
        __syncthreads();

#pragma unroll
        for (int ks = 0; ks < 4; ks++) {
            const int k8 = ks * 8;
            unsigned a[2][4], bf[4][2];
#pragma unroll
            for (int i = 0; i < 2; i++) {
                int m = wm + 16 * i + gid;
                a[i][0] = __float_as_uint(As[m][k8 + tig]);
                a[i][1] = __float_as_uint(As[m + 8][k8 + tig]);
                a[i][2] = __float_as_uint(As[m][k8 + tig + 4]);
                a[i][3] = __float_as_uint(As[m + 8][k8 + tig + 4]);
            }
#pragma unroll
            for (int j = 0; j < 4; j++) {
                int n = wn + 8 * j + gid;
                bf[j][0] = __float_as_uint(Bs[k8 + tig][n]);
                bf[j][1] = __float_as_uint(Bs[k8 + tig + 4][n]);
            }
#pragma unroll
            for (int i = 0; i < 2; i++)
#pragma unroll
                for (int j = 0; j < 4; j++)
                    mma_tf32(d[i][j], a[i], bf[j]);
        }
        __syncthreads();
    }

    float* op = part + (size_t)blockIdx.x * NR * DL;
#pragma unroll
    for (int i = 0; i < 2; i++) {
        int row = bm + wm + 16 * i + gid;
#pragma unroll
        for (int j = 0; j < 4; j++) {
            int col = wn + 8 * j + 2 * tig;
            *(float2*)(op + (size_t)row * DL + col)       = make_float2(d[i][j][0], d[i][j][1]);
            *(float2*)(op + (size_t)(row + 8) * DL + col) = make_float2(d[i][j][2], d[i][j][3]);
        }
    }
}

// Sum split-K partials + bias, LayerNorm over 64 cols. One warp per row.
__global__ __launch_bounds__(256) void ln64_k(
    const float* __restrict__ part, const float* __restrict__ bias,
    const float* __restrict__ lg, const float* __restrict__ lb,
    float* __restrict__ out, float* __restrict__ out_c)
{
    int row  = blockIdx.x * 8 + (threadIdx.x >> 5);
    int lane = threadIdx.x & 31;
    int c0 = lane, c1 = lane + 32;
    float v0 = bias[c0], v1 = bias[c1];
#pragma unroll
    for (int s = 0; s < KSPLIT; s++) {
        const float* p = part + ((size_t)s * NR + row) * DL;
        v0 += p[c0];
        v1 += p[c1];
    }
    float sm = v0 + v1;
#pragma unroll
    for (int o = 16; o; o >>= 1) sm += __shfl_xor_sync(0xffffffffu, sm, o);
    float mu = sm * (1.0f / 64.0f);
    float d0 = v0 - mu, d1 = v1 - mu;
    float sv = fmaf(d0, d0, d1 * d1);
#pragma unroll
    for (int o = 16; o; o >>= 1) sv += __shfl_xor_sync(0xffffffffu, sv, o);
    float rs = rsqrtf(sv * (1.0f / 64.0f) + 1e-9f);
    float r0 = d0 * rs * lg[c0] + lb[c0];
    float r1 = d1 * rs * lg[c1] + lb[c1];
    float* op = out + (size_t)row * DL;
    op[c0] = r0;
    op[c1] = r1;
    float* oc = out_c + (size_t)row * DL;   // tf32-rounded copy for GEMM3's A
    oc[c0] = tf32r(r0);
    oc[c1] = tf32r(r1);
}

// ---------------------------------------------------------------------------
// In-place LayerNorm over D=1024, one block per row.
// ---------------------------------------------------------------------------
__device__ __forceinline__ float block_sum_256(float v, float* red) {
#pragma unroll
    for (int o = 16; o; o >>= 1) v += __shfl_xor_sync(0xffffffffu, v, o);
    if ((threadIdx.x & 31) == 0) red[threadIdx.x >> 5] = v;
    __syncthreads();
    float t = 0.0f;
#pragma unroll
    for (int i = 0; i < 8; i++) t += red[i];
    __syncthreads();
    return t;
}

__global__ __launch_bounds__(256) void ln1024(
    float* __restrict__ x, const float* __restrict__ lg, const float* __restrict__ lb)
{
    __shared__ float red[8];
    float* p = x + (size_t)blockIdx.x * DD;
    const int tid = threadIdx.x;
    float v[4];
    float s = 0.0f;
#pragma unroll
    for (int i = 0; i < 4; i++) { v[i] = p[tid + i * 256]; s += v[i]; }
    float mu = block_sum_256(s, red) * (1.0f / 1024.0f);
    float s2 = 0.0f;
#pragma unroll
    for (int i = 0; i < 4; i++) {
        float dd = v[i] - mu;
        s2 = fmaf(dd, dd, s2);
    }
    float var = block_sum_256(s2, red) * (1.0f / 1024.0f);
    float rs = rsqrtf(var + 1e-9f);
#pragma unroll
    for (int i = 0; i < 4; i++) {
        int col = tid + i * 256;
        p[col] = (v[i] - mu) * rs * lg[col] + lb[col];
    }
}

// ---------------------------------------------------------------------------
// Per-row squared norms for DL=64 vectors.
// ---------------------------------------------------------------------------
__global__ __launch_bounds__(256) void rowsq(
    const float* __restrict__ X, float* __restrict__ o)
{
    int row = blockIdx.x * 8 + (threadIdx.x >> 5);
    int lane = threadIdx.x & 31;
    const float* p = X + (size_t)row * DL;
    float a = p[lane], b = p[lane + 32];
    float s = fmaf(a, a, b * b);
#pragma unroll
    for (int off = 16; off; off >>= 1) s += __shfl_xor_sync(0xffffffffu, s, off);
    if (lane == 0) o[row] = s;
}

// ---------------------------------------------------------------------------
// Tensor-core RBF kernel-mean tile, 128x128 per block (hi/lo tf32 split).
// ---------------------------------------------------------------------------
#define MMD_STRIDE 68
#define MMD_TILE_ELEMS (128 * MMD_STRIDE)
#define MMD_SMEM_BYTES (4 * MMD_TILE_ELEMS * 4)

__global__ __launch_bounds__(256) void mmd_tc(
    const float* __restrict__ X, const float* __restrict__ Y,
    const float* __restrict__ x2, const float* __restrict__ y2,
    double* __restrict__ acc, int sym)
{
    const int bi = blockIdx.y, bj = blockIdx.x;
    if (sym && bi > bj) return;

    extern __shared__ float smem[];
    float* Xh = smem;
    float* Xl = smem + MMD_TILE_ELEMS;
    float* Yh = smem + 2 * MMD_TILE_ELEMS;
    float* Yl = smem + 3 * MMD_TILE_ELEMS;

    const int tid  = threadIdx.x;
    const int warp = tid >> 5, lane = tid & 31;
    const int gid  = lane >> 2, tig = lane & 3;
    const int wm   = (warp & 1) * 64;
    const int wn   = (warp >> 1) * 32;
    const int i0 = bi * 128, j0 = bj * 128;

#pragma unroll
    for (int it = 0; it < 8; it++) {
        int id = tid + 256 * it;
        int r = id >> 4, c = (id & 15) << 2;
        float4 v = *(const float4*)(X + (size_t)(i0 + r) * DL + c);
        float4 h, l;
        h.x = tf32r(v.x); l.x = tf32r(v.x - h.x);
        h.y = tf32r(v.y); l.y = tf32r(v.y - h.y);
        h.z = tf32r(v.z); l.z = tf32r(v.z - h.z);
        h.w = tf32r(v.w); l.w = tf32r(v.w - h.w);
        *(float4*)&Xh[r * MMD_STRIDE + c] = h;
        *(float4*)&Xl[r * MMD_STRIDE + c] = l;
    }
#pragma unroll
    for (int it = 0; it < 8; it++) {
        int id = tid + 256 * it;
        int r = id >> 4, c = (id & 15) << 2;
        float4 v = *(const float4*)(Y + (size_t)(j0 + r) * DL + c);
        float4 h, l;
        h.x = tf32r(v.x); l.x = tf32r(v.x - h.x);
        h.y = tf32r(v.y); l.y = tf32r(v.y - h.y);
        h.z = tf32r(v.z); l.z = tf32r(v.z - h.z);
        h.w = tf32r(v.w); l.w = tf32r(v.w - h.w);
        *(float4*)&Yh[r * MMD_STRIDE + c] = h;
        *(float4*)&Yl[r * MMD_STRIDE + c] = l;
    }
    __syncthreads();

    float d[4][4][4];
#pragma unroll
    for (int i = 0; i < 4; i++)
#pragma unroll
        for (int j = 0; j < 4; j++)
#pragma unroll
            for (int r = 0; r < 4; r++) d[i][j][r] = 0.0f;

#pragma unroll
    for (int ks = 0; ks < 8; ks++) {
        const int k8 = ks * 8;
        unsigned ah[4][4], al[4][4], bh[4][2], bl[4][2];
#pragma unroll
        for (int ii = 0; ii < 4; ii++) {
            int m = wm + 16 * ii + gid;
            ah[ii][0] = __float_as_uint(Xh[m * MMD_STRIDE + k8 + tig]);
            ah[ii][1] = __float_as_uint(Xh[(m + 8) * MMD_STRIDE + k8 + tig]);
            ah[ii][2] = __float_as_uint(Xh[m * MMD_STRIDE + k8 + tig + 4]);
            ah[ii][3] = __float_as_uint(Xh[(m + 8) * MMD_STRIDE + k8 + tig + 4]);
            al[ii][0] = __float_as_uint(Xl[m * MMD_STRIDE + k8 + tig]);
            al[ii][1] = __float_as_uint(Xl[(m + 8) * MMD_STRIDE + k8 + tig]);
            al[ii][2] = __float_as_uint(Xl[m * MMD_STRIDE + k8 + tig + 4]);
            al[ii][3] = __float_as_uint(Xl[(m + 8) * MMD_STRIDE + k8 + tig + 4]);
        }
#pragma unroll
        for (int j = 0; j < 4; j++) {
            int n = wn + 8 * j + gid;
            bh[j][0] = __float_as_uint(Yh[n * MMD_STRIDE + k8 + tig]);
            bh[j][1] = __float_as_uint(Yh[n * MMD_STRIDE + k8 + tig + 4]);
            bl[j][0] = __float_as_uint(Yl[n * MMD_STRIDE + k8 + tig]);
            bl[j][1] = __float_as_uint(Yl[n * MMD_STRIDE + k8 + tig + 4]);
        }
#pragma unroll
        for (int ii = 0; ii < 4; ii++)
#pragma unroll
            for (int j = 0; j < 4; j++) {
                mma_tf32(d[ii][j], ah[ii], bh[j]);
                mma_tf32(d[ii][j], ah[ii], bl[j]);
                mma_tf32(d[ii][j], al[ii], bh[j]);
            }
    }

    float xiA[4], xiB[4], yjA[4], yjB[4];
#pragma unroll
    for (int i = 0; i < 4; i++) {
        int row = i0 + wm + 16 * i + gid;
        xiA[i] = x2[row];
        xiB[i] = x2[row + 8];
    }
#pragma unroll
    for (int j = 0; j < 4; j++) {
        int col = j0 + wn + 8 * j + 2 * tig;
        yjA[j] = y2[col];
        yjB[j] = y2[col + 1];
    }

    auto expm = [](float t) {
        float e = fmaf(t, -1.0f / 720.0f, 1.0f / 120.0f);
        e = fmaf(t, e, -1.0f / 24.0f);
        e = fmaf(t, e, 1.0f / 6.0f);
        e = fmaf(t, e, -0.5f);
        e = fmaf(t, e, 1.0f);
        e = fmaf(-t, e, 1.0f);
        if (t > 0.5f) e = __expf(-t);
        return e;
    };

    float lsum = 0.0f;
#pragma unroll
    for (int i = 0; i < 4; i++)
#pragma unroll
        for (int j = 0; j < 4; j++) {
            float s0 = xiA[i] + yjA[j] - 2.0f * d[i][j][0];
            float s1 = xiA[i] + yjB[j] - 2.0f * d[i][j][1];
            float s2 = xiB[i] + yjA[j] - 2.0f * d[i][j][2];
            float s3 = xiB[i] + yjB[j] - 2.0f * d[i][j][3];
            lsum += expm(s0 * (1.0f / 4096.0f));
            lsum += expm(s1 * (1.0f / 4096.0f));
            lsum += expm(s2 * (1.0f / 4096.0f));
            lsum += expm(s3 * (1.0f / 4096.0f));
        }

    if (sym && bi != bj) lsum *= 2.0f;

#pragma unroll
    for (int off = 16; off; off >>= 1)
        lsum += __shfl_xor_sync(0xffffffffu, lsum, off);

    __shared__ float ws[8];
    if ((tid & 31) == 0) ws[tid >> 5] = lsum;
    __syncthreads();
    if (tid == 0) {
        double t = 0.0;
#pragma unroll
        for (int w = 0; w < 8; w++) t += (double)ws[w];
        atomicAdd(acc, t);
    }
}

__global__ void zero_acc_k() {
    if (threadIdx.x < 3) g_acc[threadIdx.x] = 0.0;
}

__global__ void finalize_loss(float* __restrict__ out) {
    const double inv = 1.0 / (4096.0 * 4096.0);
    double mmd = (g_acc[0] + g_acc[1] - 2.0 * g_acc[2]) * inv;
    out[0] = (float)(mmd * 64.0);
}

// ---------------------------------------------------------------------------
extern "C" void kernel_launch(void* const* d_in, const int* in_sizes, int n_in,
                              void* d_out, int out_size)
{
    const float* hidden = (const float*)d_in[0];
    const float* true_s = (const float*)d_in[1];
    const float* enc_w1 = (const float*)d_in[2];
    const float* enc_b1 = (const float*)d_in[3];
    const float* enc_w2 = (const float*)d_in[4];
    const float* enc_b2 = (const float*)d_in[5];
    const float* enc_g  = (const float*)d_in[6];
    const float* enc_lb = (const float*)d_in[7];
    const float* dec_w1 = (const float*)d_in[8];
    const float* dec_b1 = (const float*)d_in[9];
    const float* dec_w2 = (const float*)d_in[10];
    const float* dec_b2 = (const float*)d_in[11];
    const float* dec_g  = (const float*)d_in[12];
    const float* dec_lb = (const float*)d_in[13];

    float* recon  = (float*)d_out;
    float* latent = recon + (size_t)NR * DD;
    float* loss   = latent + (size_t)NR * DL;

    float*  h;    cudaGetSymbolAddress((void**)&h,    g_h);
    float*  part; cudaGetSymbolAddress((void**)&part, g_part);
    float*  hidc; cudaGetSymbolAddress((void**)&hidc, g_hidc);
    float*  wc1;  cudaGetSymbolAddress((void**)&wc1,  g_wc1);
    float*  dw1;  cudaGetSymbolAddress((void**)&dw1,  g_dw1);
    float*  dw2;  cudaGetSymbolAddress((void**)&dw2,  g_dw2);
    float*  latc; cudaGetSymbolAddress((void**)&latc, g_latc);
    float*  x2;   cudaGetSymbolAddress((void**)&x2,   g_x2);
    float*  y2;   cudaGetSymbolAddress((void**)&y2,   g_y2);
    double* acc;  cudaGetSymbolAddress((void**)&acc,  g_acc);

    static int attr_set = 0;
    if (!attr_set) {
        cudaFuncSetAttribute(gemm_tc<true, true>,
                             cudaFuncAttributeMaxDynamicSharedMemorySize,
                             GEMM_SMEM_BYTES);
        cudaFuncSetAttribute(gemm_tc<false, false>,
                             cudaFuncAttributeMaxDynamicSharedMemorySize,
                             GEMM_SMEM_BYTES);
        cudaFuncSetAttribute(mmd_tc,
                             cudaFuncAttributeMaxDynamicSharedMemorySize,
                             MMD_SMEM_BYTES);
        attr_set = 1;
    }

    zero_acc_k<<<1, 32>>>();

    // pre-pass: tf32-round the GEMM inputs once
    cvt_tf32_k<<<(NR * DD / 4 + 255) / 256, 256>>>(hidden, hidc, NR * DD / 4);
    cvt_tf32_k<<<(DD * DI / 4 + 255) / 256, 256>>>(enc_w1, wc1, DD * DI / 4);
    cvt_tf32_k<<<(DL * DI / 4 + 255) / 256, 256>>>(dec_w1, dw1, DL * DI / 4);
    cvt_tf32_k<<<(DI * DD / 4 + 255) / 256, 256>>>(dec_w2, dw2, DI * DD / 4);

    // encoder: h = tf32(gelu(hidden @ enc_w1 + b1))   [4096,4096]
    gemm_tc<true, true><<<dim3(DI / 128, NR / 128), 128, GEMM_SMEM_BYTES>>>(
        hidc, wc1, enc_b1, h, NR, DI, DD);
    // latent = LN64(h @ enc_w2 + b2)  (split-K + fused LN); also tf32 copy
    gemm2_tc<<<dim3(KSPLIT, NR / 128), 256>>>(h, enc_w2, part);
    ln64_k<<<NR / 8, 256>>>(part, enc_b2, enc_g, enc_lb, latent, latc);

    // decoder
    gemm_tc<true, true><<<dim3(DI / 128, NR / 128), 128, GEMM_SMEM_BYTES>>>(
        latc, dw1, dec_b1, h, NR, DI, DL);
    gemm_tc<false, false><<<dim3(DD / 128, NR / 128), 128, GEMM_SMEM_BYTES>>>(
        h, dw2, dec_b2, recon, NR, DD, DI);
    ln1024<<<NR, 256>>>(recon, dec_g, dec_lb);

    // MMD (full-precision latent; tensor-core Gram with hi/lo split)
    rowsq<<<NR / 8, 256>>>(true_s, x2);
    rowsq<<<NR / 8, 256>>>(latent, y2);
    mmd_tc<<<dim3(32, 32), 256, MMD_SMEM_BYTES>>>(true_s, true_s, x2, x2, acc + 0, 1);
    mmd_tc<<<dim3(32, 32), 256, MMD_SMEM_BYTES>>>(latent, latent, y2, y2, acc + 1, 1);
    mmd_tc<<<dim3(32, 32), 256, MMD_SMEM_BYTES>>>(true_s, latent, x2, y2, acc + 2, 0);
    finalize_loss<<<1, 1>>>(loss);
}

// round 16
// speedup vs baseline: 1.1270x; 1.1270x over previous
#include <cuda_runtime.h>
#include <math.h>
#include <stdint.h>

#define NR 4096
#define DD 1024
#define DI 4096
#define DL 64
#define KSPLIT 8

// scratch
__device__ float g_h[(size_t)4096 * 4096];           // 64MB hidden activations (tf32-rounded)
__device__ float g_part[(size_t)KSPLIT * 4096 * 64]; // 8MB split-K partials
__device__ float g_hidc[(size_t)NR * DD];            // hidden input, tf32-rounded
__device__ float g_wc1[(size_t)DD * DI];             // enc_w1, tf32-rounded
__device__ float g_dw1[(size_t)DL * DI];             // dec_w1, tf32-rounded
__device__ float g_dw2[(size_t)DI * DD];             // dec_w2, tf32-rounded
__device__ float g_latc[(size_t)NR * DL];            // latent, tf32-rounded
__device__ float g_x2[4096];
__device__ float g_y2[4096];
__device__ double g_acc[3];

__device__ __forceinline__ float gelu_f(float x) {
    return 0.5f * x * (1.0f + erff(x * 0.70710678118654752440f));
}

__device__ __forceinline__ unsigned f2tf32(float x) {
    unsigned u;
    asm("cvt.rna.tf32.f32 %0, %1;" : "=r"(u) : "f"(x));
    return u;
}
__device__ __forceinline__ float tf32r(float x) { return __uint_as_float(f2tf32(x)); }

__device__ __forceinline__ void mma_tf32(float* d, const unsigned* a, const unsigned* b) {
    asm volatile(
        "mma.sync.aligned.m16n8k8.row.col.f32.tf32.tf32.f32 "
        "{%0,%1,%2,%3}, {%4,%5,%6,%7}, {%8,%9}, {%0,%1,%2,%3};\n"
        : "+f"(d[0]), "+f"(d[1]), "+f"(d[2]), "+f"(d[3])
        : "r"(a[0]), "r"(a[1]), "r"(a[2]), "r"(a[3]), "r"(b[0]), "r"(b[1]));
}

__device__ __forceinline__ void cp16(float* dst_smem, const float* src) {
    unsigned d = (unsigned)__cvta_generic_to_shared(dst_smem);
    asm volatile("cp.async.cg.shared.global [%0], [%1], 16;\n" :: "r"(d), "l"(src));
}

// elementwise tf32-round copy (float4 vectorized); n multiple of 4
__global__ __launch_bounds__(256) void cvt_tf32_k(
    const float* __restrict__ in, float* __restrict__ out, int n4)
{
    int i = blockIdx.x * 256 + threadIdx.x;
    if (i < n4) {
        float4 v = ((const float4*)in)[i];
        float4 w;
        w.x = tf32r(v.x); w.y = tf32r(v.y);
        w.z = tf32r(v.z); w.w = tf32r(v.w);
        ((float4*)out)[i] = w;
    }
}

// smem layout constants for the pipelined GEMM
#define AS_STRIDE 36
#define BS_STRIDE 136
#define AS_ELEMS (128 * AS_STRIDE)   // per stage
#define BS_ELEMS (32 * BS_STRIDE)    // per stage
#define NSTAGES 3
#define GEMM_SMEM_BYTES (NSTAGES * (AS_ELEMS + BS_ELEMS) * 4)

// ---------------------------------------------------------------------------
// TF32 tensor-core GEMM, 3-stage cp.async pipeline (R7 config: 8 warps, 2m x 4n).
// Inputs MUST already be tf32-rounded fp32; mainloop is pure LDS + MMA.
// ---------------------------------------------------------------------------
template <bool GELU, bool CVT_OUT>
__global__ __launch_bounds__(256, 2) void gemm_tc(
    const float* __restrict__ A, const float* __restrict__ B,
    const float* __restrict__ bias, float* __restrict__ C,
    int M, int N, int K)
{
    extern __shared__ float smem[];
    float* Asm = smem;
    float* Bsm = smem + NSTAGES * AS_ELEMS;

    const int tid  = threadIdx.x;
    const int warp = tid >> 5, lane = tid & 31;
    const int gid  = lane >> 2, tig = lane & 3;
    const int wm   = (warp & 1) * 64;
    const int wn   = (warp >> 1) * 32;
    const int bm   = blockIdx.y * 128;
    const int bn   = blockIdx.x * 128;

    auto load_stage = [&](int k0, int s) {
        float* a = Asm + s * AS_ELEMS;
        float* b = Bsm + s * BS_ELEMS;
#pragma unroll
        for (int it = 0; it < 4; it++) {
            int id = tid + 256 * it;
            int r = id >> 3, c = (id & 7) << 2;
            cp16(a + r * AS_STRIDE + c, A + (size_t)(bm + r) * K + k0 + c);
        }
#pragma unroll
        for (int it = 0; it < 4; it++) {
            int id = tid + 256 * it;
            int r = id >> 5, c = (id & 31) << 2;
            cp16(b + r * BS_STRIDE + c, B + (size_t)(k0 + r) * N + bn + c);
        }
        asm volatile("cp.async.commit_group;\n");
    };

    float d[4][4][4];
#pragma unroll
    for (int i = 0; i < 4; i++)
#pragma unroll
        for (int j = 0; j < 4; j++)
#pragma unroll
            for (int r = 0; r < 4; r++) d[i][j][r] = 0.0f;

    const int T = K >> 5;
    load_stage(0, 0);
    if (T > 1) load_stage(32, 1);

    for (int i = 0; i < T; i++) {
        if (i + 1 < T) {
            asm volatile("cp.async.wait_group 1;\n");
        } else {
            asm volatile("cp.async.wait_group 0;\n");
        }
        __syncthreads();

        const float* a = Asm + (i % NSTAGES) * AS_ELEMS;
        const float* b = Bsm + (i % NSTAGES) * BS_ELEMS;

#pragma unroll
        for (int ks = 0; ks < 4; ks++) {
            const int k8 = ks * 8;
            unsigned af[4][4], bf[4][2];
#pragma unroll
            for (int ii = 0; ii < 4; ii++) {
                int m = wm + 16 * ii + gid;
                af[ii][0] = __float_as_uint(a[m * AS_STRIDE + k8 + tig]);
                af[ii][1] = __float_as_uint(a[(m + 8) * AS_STRIDE + k8 + tig]);
                af[ii][2] = __float_as_uint(a[m * AS_STRIDE + k8 + tig + 4]);
                af[ii][3] = __float_as_uint(a[(m + 8) * AS_STRIDE + k8 + tig + 4]);
            }
#pragma unroll
            for (int j = 0; j < 4; j++) {
                int n = wn + 8 * j + gid;
                bf[j][0] = __float_as_uint(b[(k8 + tig) * BS_STRIDE + n]);
                bf[j][1] = __float_as_uint(b[(k8 + tig + 4) * BS_STRIDE + n]);
            }
#pragma unroll
            for (int ii = 0; ii < 4; ii++)
#pragma unroll
                for (int j = 0; j < 4; j++)
                    mma_tf32(d[ii][j], af[ii], bf[j]);
        }

        if (i + 2 < T) load_stage((i + 2) * 32, (i + 2) % NSTAGES);
    }

#pragma unroll
    for (int i = 0; i < 4; i++) {
        int row = bm + wm + 16 * i + gid;
#pragma unroll
        for (int j = 0; j < 4; j++) {
            int col = bn + wn + 8 * j + 2 * tig;
            float bx = bias[col], by = bias[col + 1];
            float r0 = d[i][j][0] + bx, r1 = d[i][j][1] + by;
            float r2 = d[i][j][2] + bx, r3 = d[i][j][3] + by;
            if (GELU) {
                r0 = gelu_f(r0); r1 = gelu_f(r1);
                r2 = gelu_f(r2); r3 = gelu_f(r3);
            }
            if (CVT_OUT) {
                r0 = tf32r(r0); r1 = tf32r(r1);
                r2 = tf32r(r2); r3 = tf32r(r3);
            }
            *(float2*)(C + (size_t)row * N + col)       = make_float2(r0, r1);
            *(float2*)(C + (size_t)(row + 8) * N + col) = make_float2(r2, r3);
        }
    }
}

// ---------------------------------------------------------------------------
// GEMM2 split-K (tf32): part[ks][4096,64] = A[:,ks*512:+512] @ B-slice
// ---------------------------------------------------------------------------
__global__ __launch_bounds__(256, 2) void gemm2_tc(
    const float* __restrict__ A, const float* __restrict__ B,
    float* __restrict__ part)
{
    __shared__ float As[128][36];
    __shared__ float Bs[32][72];

    const int tid  = threadIdx.x;
    const int warp = tid >> 5, lane = tid & 31;
    const int gid  = lane >> 2, tig = lane & 3;
    const int wm   = (warp & 3) * 32;
    const int wn   = (warp >> 2) * 32;
    const int bm   = blockIdx.y * 128;
    const int kbeg = blockIdx.x * (DI / KSPLIT);

    float d[2][4][4];
#pragma unroll
    for (int i = 0; i < 2; i++)
#pragma unroll
        for (int j = 0; j < 4; j++)
#pragma unroll
            for (int r = 0; r < 4; r++) d[i][j][r] = 0.0f;

    for (int kk = 0; kk < DI / KSPLIT; kk += 32) {
        const int k0 = kbeg + kk;
#pragma unroll
        for (int it = 0; it < 4; it++) {
            int id = tid + 256 * it;
            int r = id >> 3, c = (id & 7) << 2;
            *(float4*)&As[r][c] =
                *(const float4*)(A + (size_t)(bm + r) * DI + k0 + c);
        }
#pragma unroll
        for (int it = 0; it < 2; it++) {
            int id = tid + 256 * it;
            int r = id >> 4, c = (id & 15) << 2;
            float4 v = *(const float4*)(B + (size_t)(k0 + r) * DL + c);
            float4 w;
            w.x = tf32r(v.x); w.y = tf32r(v.y);
            w.z = tf32r(v.z); w.w = tf32r(v.w);
            *(float4*)&Bs[r][c] = w;
        }
        __syncthreads();

#pragma unroll
        for (int ks = 0; ks < 4; ks++) {
            const int k8 = ks * 8;
            unsigned a[2][4], bf[4][2];
#pragma unroll
            for (int i = 0; i < 2; i++) {
                int m = wm + 16 * i + gid;
                a[i][0] = __float_as_uint(As[m][k8 + tig]);
                a[i][1] = __float_as_uint(As[m + 8][k8 + tig]);
                a[i][2] = __float_as_uint(As[m][k8 + tig + 4]);
                a[i][3] = __float_as_uint(As[m + 8][k8 + tig + 4]);
            }
#pragma unroll
            for (int j = 0; j < 4; j++) {
                int n = wn + 8 * j + gid;
                bf[j][0] = __float_as_uint(Bs[k8 + tig][n]);
                bf[j][1] = __float_as_uint(Bs[k8 + tig + 4][n]);
            }
#pragma unroll
            for (int i = 0; i < 2; i++)
#pragma unroll
                for (int j = 0; j < 4; j++)
                    mma_tf32(d[i][j], a[i], bf[j]);
        }
        __syncthreads();
    }

    float* op = part + (size_t)blockIdx.x * NR * DL;
#pragma unroll
    for (int i = 0; i < 2; i++) {
        int row = bm + wm + 16 * i + gid;
#pragma unroll
        for (int j = 0; j < 4; j++) {
            int col = wn + 8 * j + 2 * tig;
            *(float2*)(op + (size_t)row * DL + col)       = make_float2(d[i][j][0], d[i][j][1]);
            *(float2*)(op + (size_t)(row + 8) * DL + col) = make_float2(d[i][j][2], d[i][j][3]);
        }
    }
}

// Sum split-K partials + bias, LayerNorm over 64 cols. One warp per row.
__global__ __launch_bounds__(256) void ln64_k(
    const float* __restrict__ part, const float* __restrict__ bias,
    const float* __restrict__ lg, const float* __restrict__ lb,
    float* __restrict__ out, float* __restrict__ out_c)
{
    int row  = blockIdx.x * 8 + (threadIdx.x >> 5);
    int lane = threadIdx.x & 31;
    int c0 = lane, c1 = lane + 32;
    float v0 = bias[c0], v1 = bias[c1];
#pragma unroll
    for (int s = 0; s < KSPLIT; s++) {
        const float* p = part + ((size_t)s * NR + row) * DL;
        v0 += p[c0];
        v1 += p[c1];
    }
    float sm = v0 + v1;
#pragma unroll
    for (int o = 16; o; o >>= 1) sm += __shfl_xor_sync(0xffffffffu, sm, o);
    float mu = sm * (1.0f / 64.0f);
    float d0 = v0 - mu, d1 = v1 - mu;
    float sv = fmaf(d0, d0, d1 * d1);
#pragma unroll
    for (int o = 16; o; o >>= 1) sv += __shfl_xor_sync(0xffffffffu, sv, o);
    float rs = rsqrtf(sv * (1.0f / 64.0f) + 1e-9f);
    float r0 = d0 * rs * lg[c0] + lb[c0];
    float r1 = d1 * rs * lg[c1] + lb[c1];
    float* op = out + (size_t)row * DL;
    op[c0] = r0;
    op[c1] = r1;
    float* oc = out_c + (size_t)row * DL;   // tf32-rounded copy for GEMM3's A
    oc[c0] = tf32r(r0);
    oc[c1] = tf32r(r1);
}

// ---------------------------------------------------------------------------
// In-place LayerNorm over D=1024, one block per row.
// ---------------------------------------------------------------------------
__device__ __forceinline__ float block_sum_256(float v, float* red) {
#pragma unroll
    for (int o = 16; o; o >>= 1) v += __shfl_xor_sync(0xffffffffu, v, o);
    if ((threadIdx.x & 31) == 0) red[threadIdx.x >> 5] = v;
    __syncthreads();
    float t = 0.0f;
#pragma unroll
    for (int i = 0; i < 8; i++) t += red[i];
    __syncthreads();
    return t;
}

__global__ __launch_bounds__(256) void ln1024(
    float* __restrict__ x, const float* __restrict__ lg, const float* __restrict__ lb)
{
    __shared__ float red[8];
    float* p = x + (size_t)blockIdx.x * DD;
    const int tid = threadIdx.x;
    float v[4];
    float s = 0.0f;
#pragma unroll
    for (int i = 0; i < 4; i++) { v[i] = p[tid + i * 256]; s += v[i]; }
    float mu = block_sum_256(s, red) * (1.0f / 1024.0f);
    float s2 = 0.0f;
#pragma unroll
    for (int i = 0; i < 4; i++) {
        float dd = v[i] - mu;
        s2 = fmaf(dd, dd, s2);
    }
    float var = block_sum_256(s2, red) * (1.0f / 1024.0f);
    float rs = rsqrtf(var + 1e-9f);
#pragma unroll
    for (int i = 0; i < 4; i++) {
        int col = tid + i * 256;
        p[col] = (v[i] - mu) * rs * lg[col] + lb[col];
    }
}

// ---------------------------------------------------------------------------
// Per-row squared norms for DL=64 vectors.
// ---------------------------------------------------------------------------
__global__ __launch_bounds__(256) void rowsq(
    const float* __restrict__ X, float* __restrict__ o)
{
    int row = blockIdx.x * 8 + (threadIdx.x >> 5);
    int lane = threadIdx.x & 31;
    const float* p = X + (size_t)row * DL;
    float a = p[lane], b = p[lane + 32];
    float s = fmaf(a, a, b * b);
#pragma unroll
    for (int off = 16; off; off >>= 1) s += __shfl_xor_sync(0xffffffffu, s, off);
    if (lane == 0) o[row] = s;
}

// ---------------------------------------------------------------------------
// Tensor-core RBF kernel-mean tile, 128x128 per block (hi/lo tf32 split).
// ---------------------------------------------------------------------------
#define MMD_STRIDE 68
#define MMD_TILE_ELEMS (128 * MMD_STRIDE)
#define MMD_SMEM_BYTES (4 * MMD_TILE_ELEMS * 4)

__global__ __launch_bounds__(256) void mmd_tc(
    const float* __restrict__ X, const float* __restrict__ Y,
    const float* __restrict__ x2, const float* __restrict__ y2,
    double* __restrict__ acc, int sym)
{
    const int bi = blockIdx.y, bj = blockIdx.x;
    if (sym && bi > bj) return;

    extern __shared__ float smem[];
    float* Xh = smem;
    float* Xl = smem + MMD_TILE_ELEMS;
    float* Yh = smem + 2 * MMD_TILE_ELEMS;
    float* Yl = smem + 3 * MMD_TILE_ELEMS;

    const int tid  = threadIdx.x;
    const int warp = tid >> 5, lane = tid & 31;
    const int gid  = lane >> 2, tig = lane & 3;
    const int wm   = (warp & 1) * 64;
    const int wn   = (warp >> 1) * 32;
    const int i0 = bi * 128, j0 = bj * 128;

#pragma unroll
    for (int it = 0; it < 8; it++) {
        int id = tid + 256 * it;
        int r = id >> 4, c = (id & 15) << 2;
        float4 v = *(const float4*)(X + (size_t)(i0 + r) * DL + c);
        float4 h, l;
        h.x = tf32r(v.x); l.x = tf32r(v.x - h.x);
        h.y = tf32r(v.y); l.y = tf32r(v.y - h.y);
        h.z = tf32r(v.z); l.z = tf32r(v.z - h.z);
        h.w = tf32r(v.w); l.w = tf32r(v.w - h.w);
        *(float4*)&Xh[r * MMD_STRIDE + c] = h;
        *(float4*)&Xl[r * MMD_STRIDE + c] = l;
    }
#pragma unroll
    for (int it = 0; it < 8; it++) {
        int id = tid + 256 * it;
        int r = id >> 4, c = (id & 15) << 2;
        float4 v = *(const float4*)(Y + (size_t)(j0 + r) * DL + c);
        float4 h, l;
        h.x = tf32r(v.x); l.x = tf32r(v.x - h.x);
        h.y = tf32r(v.y); l.y = tf32r(v.y - h.y);
        h.z = tf32r(v.z); l.z = tf32r(v.z - h.z);
        h.w = tf32r(v.w); l.w = tf32r(v.w - h.w);
        *(float4*)&Yh[r * MMD_STRIDE + c] = h;
        *(float4*)&Yl[r * MMD_STRIDE + c] = l;
    }
    __syncthreads();

    float d[4][4][4];
#pragma unroll
    for (int i = 0; i < 4; i++)
#pragma unroll
        for (int j = 0; j < 4; j++)
#pragma unroll
            for (int r = 0; r < 4; r++) d[i][j][r] = 0.0f;

#pragma unroll
    for (int ks = 0; ks < 8; ks++) {
        const int k8 = ks * 8;
        unsigned ah[4][4], al[4][4], bh[4][2], bl[4][2];
#pragma unroll
        for (int ii = 0; ii < 4; ii++) {
            int m = wm + 16 * ii + gid;
            ah[ii][0] = __float_as_uint(Xh[m * MMD_STRIDE + k8 + tig]);
            ah[ii][1] = __float_as_uint(Xh[(m + 8) * MMD_STRIDE + k8 + tig]);
            ah[ii][2] = __float_as_uint(Xh[m * MMD_STRIDE + k8 + tig + 4]);
            ah[ii][3] = __float_as_uint(Xh[(m + 8) * MMD_STRIDE + k8 + tig + 4]);
            al[ii][0] = __float_as_uint(Xl[m * MMD_STRIDE + k8 + tig]);
            al[ii][1] = __float_as_uint(Xl[(m + 8) * MMD_STRIDE + k8 + tig]);
            al[ii][2] = __float_as_uint(Xl[m * MMD_STRIDE + k8 + tig + 4]);
            al[ii][3] = __float_as_uint(Xl[(m + 8) * MMD_STRIDE + k8 + tig + 4]);
        }
#pragma unroll
        for (int j = 0; j < 4; j++) {
            int n = wn + 8 * j + gid;
            bh[j][0] = __float_as_uint(Yh[n * MMD_STRIDE + k8 + tig]);
            bh[j][1] = __float_as_uint(Yh[n * MMD_STRIDE + k8 + tig + 4]);
            bl[j][0] = __float_as_uint(Yl[n * MMD_STRIDE + k8 + tig]);
            bl[j][1] = __float_as_uint(Yl[n * MMD_STRIDE + k8 + tig + 4]);
        }
#pragma unroll
        for (int ii = 0; ii < 4; ii++)
#pragma unroll
            for (int j = 0; j < 4; j++) {
                mma_tf32(d[ii][j], ah[ii], bh[j]);
                mma_tf32(d[ii][j], ah[ii], bl[j]);
                mma_tf32(d[ii][j], al[ii], bh[j]);
            }
    }

    float xiA[4], xiB[4], yjA[4], yjB[4];
#pragma unroll
    for (int i = 0; i < 4; i++) {
        int row = i0 + wm + 16 * i + gid;
        xiA[i] = x2[row];
        xiB[i] = x2[row + 8];
    }
#pragma unroll
    for (int j = 0; j < 4; j++) {
        int col = j0 + wn + 8 * j + 2 * tig;
        yjA[j] = y2[col];
        yjB[j] = y2[col + 1];
    }

    auto expm = [](float t) {
        float e = fmaf(t, -1.0f / 720.0f, 1.0f / 120.0f);
        e = fmaf(t, e, -1.0f / 24.0f);
        e = fmaf(t, e, 1.0f / 6.0f);
        e = fmaf(t, e, -0.5f);
        e = fmaf(t, e, 1.0f);
        e = fmaf(-t, e, 1.0f);
        if (t > 0.5f) e = __expf(-t);
        return e;
    };

    float lsum = 0.0f;
#pragma unroll
    for (int i = 0; i < 4; i++)
#pragma unroll
        for (int j = 0; j < 4; j++) {
            float s0 = xiA[i] + yjA[j] - 2.0f * d[i][j][0];
            float s1 = xiA[i] + yjB[j] - 2.0f * d[i][j][1];
            float s2 = xiB[i] + yjA[j] - 2.0f * d[i][j][2];
            float s3 = xiB[i] + yjB[j] - 2.0f * d[i][j][3];
            lsum += expm(s0 * (1.0f / 4096.0f));
            lsum += expm(s1 * (1.0f / 4096.0f));
            lsum += expm(s2 * (1.0f / 4096.0f));
            lsum += expm(s3 * (1.0f / 4096.0f));
        }

    if (sym && bi != bj) lsum *= 2.0f;

#pragma unroll
    for (int off = 16; off; off >>= 1)
        lsum += __shfl_xor_sync(0xffffffffu, lsum, off);

    __shared__ float ws[8];
    if ((tid & 31) == 0) ws[tid >> 5] = lsum;
    __syncthreads();
    if (tid == 0) {
        double t = 0.0;
#pragma unroll
        for (int w = 0; w < 8; w++) t += (double)ws[w];
        atomicAdd(acc, t);
    }
}

__global__ void zero_acc_k() {
    if (threadIdx.x < 3) g_acc[threadIdx.x] = 0.0;
}

__global__ void finalize_loss(float* __restrict__ out) {
    const double inv = 1.0 / (4096.0 * 4096.0);
    double mmd = (g_acc[0] + g_acc[1] - 2.0 * g_acc[2]) * inv;
    out[0] = (float)(mmd * 64.0);
}

// ---------------------------------------------------------------------------
extern "C" void kernel_launch(void* const* d_in, const int* in_sizes, int n_in,
                              void* d_out, int out_size)
{
    const float* hidden = (const float*)d_in[0];
    const float* true_s = (const float*)d_in[1];
    const float* enc_w1 = (const float*)d_in[2];
    const float* enc_b1 = (const float*)d_in[3];
    const float* enc_w2 = (const float*)d_in[4];
    const float* enc_b2 = (const float*)d_in[5];
    const float* enc_g  = (const float*)d_in[6];
    const float* enc_lb = (const float*)d_in[7];
    const float* dec_w1 = (const float*)d_in[8];
    const float* dec_b1 = (const float*)d_in[9];
    const float* dec_w2 = (const float*)d_in[10];
    const float* dec_b2 = (const float*)d_in[11];
    const float* dec_g  = (const float*)d_in[12];
    const float* dec_lb = (const float*)d_in[13];

    float* recon  = (float*)d_out;
    float* latent = recon + (size_t)NR * DD;
    float* loss   = latent + (size_t)NR * DL;

    float*  h;    cudaGetSymbolAddress((void**)&h,    g_h);
    float*  part; cudaGetSymbolAddress((void**)&part, g_part);
    float*  hidc; cudaGetSymbolAddress((void**)&hidc, g_hidc);
    float*  wc1;  cudaGetSymbolAddress((void**)&wc1,  g_wc1);
    float*  dw1;  cudaGetSymbolAddress((void**)&dw1,  g_dw1);
    float*  dw2;  cudaGetSymbolAddress((void**)&dw2,  g_dw2);
    float*  latc; cudaGetSymbolAddress((void**)&latc, g_latc);
    float*  x2;   cudaGetSymbolAddress((void**)&x2,   g_x2);
    float*  y2;   cudaGetSymbolAddress((void**)&y2,   g_y2);
    double* acc;  cudaGetSymbolAddress((void**)&acc,  g_acc);

    static cudaStream_t s1 = nullptr, s2 = nullptr;
    static cudaEvent_t e0, e_lat, e_w, e_end;
    if (!s1) {
        cudaStreamCreateWithFlags(&s1, cudaStreamNonBlocking);
        cudaStreamCreateWithFlags(&s2, cudaStreamNonBlocking);
        cudaEventCreateWithFlags(&e0,    cudaEventDisableTiming);
        cudaEventCreateWithFlags(&e_lat, cudaEventDisableTiming);
        cudaEventCreateWithFlags(&e_w,   cudaEventDisableTiming);
        cudaEventCreateWithFlags(&e_end, cudaEventDisableTiming);
        cudaFuncSetAttribute(gemm_tc<true, true>,
                             cudaFuncAttributeMaxDynamicSharedMemorySize,
                             GEMM_SMEM_BYTES);
        cudaFuncSetAttribute(gemm_tc<false, false>,
                             cudaFuncAttributeMaxDynamicSharedMemorySize,
                             GEMM_SMEM_BYTES);
        cudaFuncSetAttribute(mmd_tc,
                             cudaFuncAttributeMaxDynamicSharedMemorySize,
                             MMD_SMEM_BYTES);
    }

    // root (captured origin stream)
    zero_acc_k<<<1, 32>>>();
    cudaEventRecord(e0, 0);

    // ---- branch s1: input-only MMD work (overlaps encoder GEMM1) ----
    cudaStreamWaitEvent(s1, e0, 0);
    rowsq<<<NR / 8, 256, 0, s1>>>(true_s, x2);
    mmd_tc<<<dim3(32, 32), 256, MMD_SMEM_BYTES, s1>>>(true_s, true_s, x2, x2,
                                                      acc + 0, 1);

    // ---- branch s2: decoder weight cvts (overlap encoder GEMM1) ----
    cudaStreamWaitEvent(s2, e0, 0);
    cvt_tf32_k<<<(DL * DI / 4 + 255) / 256, 256, 0, s2>>>(dec_w1, dw1, DL * DI / 4);
    cvt_tf32_k<<<(DI * DD / 4 + 255) / 256, 256, 0, s2>>>(dec_w2, dw2, DI * DD / 4);
    cudaEventRecord(e_w, s2);

    // ---- main stream: encoder ----
    cvt_tf32_k<<<(NR * DD / 4 + 255) / 256, 256>>>(hidden, hidc, NR * DD / 4);
    cvt_tf32_k<<<(DD * DI / 4 + 255) / 256, 256>>>(enc_w1, wc1, DD * DI / 4);
    gemm_tc<true, true><<<dim3(DI / 128, NR / 128), 256, GEMM_SMEM_BYTES>>>(
        hidc, wc1, enc_b1, h, NR, DI, DD);
    gemm2_tc<<<dim3(KSPLIT, NR / 128), 256>>>(h, enc_w2, part);
    ln64_k<<<NR / 8, 256>>>(part, enc_b2, enc_g, enc_lb, latent, latc);
    cudaEventRecord(e_lat, 0);

    // ---- branch s1: latent-dependent MMD (overlaps decoder GEMMs) ----
    cudaStreamWaitEvent(s1, e_lat, 0);
    rowsq<<<NR / 8, 256, 0, s1>>>(latent, y2);
    mmd_tc<<<dim3(32, 32), 256, MMD_SMEM_BYTES, s1>>>(latent, latent, y2, y2,
                                                      acc + 1, 1);
    mmd_tc<<<dim3(32, 32), 256, MMD_SMEM_BYTES, s1>>>(true_s, latent, x2, y2,
                                                      acc + 2, 0);
    finalize_loss<<<1, 1, 0, s1>>>(loss);
    cudaEventRecord(e_end, s1);

    // ---- main stream: decoder ----
    cudaStreamWaitEvent(0, e_w, 0);
    gemm_tc<true, true><<<dim3(DI / 128, NR / 128), 256, GEMM_SMEM_BYTES>>>(
        latc, dw1, dec_b1, h, NR, DI, DL);
    gemm_tc<false, false><<<dim3(DD / 128, NR / 128), 256, GEMM_SMEM_BYTES>>>(
        h, dw2, dec_b2, recon, NR, DD, DI);
    ln1024<<<NR, 256>>>(recon, dec_g, dec_lb);

    // join MMD branch before returning
    cudaStreamWaitEvent(0, e_end, 0);
}

// round 17
// speedup vs baseline: 1.5120x; 1.3416x over previous
#include <cuda_runtime.h>
#include <cuda_fp16.h>
#include <math.h>
#include <stdint.h>

#define NR 4096
#define DD 1024
#define DI 4096
#define DL 64
#define KSPLIT 8

// scratch
__device__ __half g_hh[(size_t)NR * DI];          // 32MB hidden activations (fp16)
__device__ float  g_part[(size_t)KSPLIT * NR * DL]; // 8MB split-K partials (fp32)
__device__ __half g_hidh[(size_t)NR * DD];        // hidden input, fp16
__device__ __half g_w1t[(size_t)DI * DD];         // enc_w1^T  [DI][DD] fp16
__device__ __half g_w2t[(size_t)DL * DI];         // enc_w2^T  [DL][DI] fp16
__device__ __half g_d1t[(size_t)DI * DL];         // dec_w1^T  [DI][DL] fp16
__device__ __half g_d2t[(size_t)DD * DI];         // dec_w2^T  [DD][DI] fp16
__device__ __half g_lath[(size_t)NR * DL];        // latent, fp16
__device__ float  g_x2[4096];
__device__ float  g_y2[4096];
__device__ double g_acc[3];

__device__ __forceinline__ float gelu_f(float x) {
    return 0.5f * x * (1.0f + erff(x * 0.70710678118654752440f));
}

__device__ __forceinline__ unsigned f2tf32(float x) {
    unsigned u;
    asm("cvt.rna.tf32.f32 %0, %1;" : "=r"(u) : "f"(x));
    return u;
}
__device__ __forceinline__ float tf32r(float x) { return __uint_as_float(f2tf32(x)); }

// tf32 mma (used by MMD hi/lo path only)
__device__ __forceinline__ void mma_tf32(float* d, const unsigned* a, const unsigned* b) {
    asm volatile(
        "mma.sync.aligned.m16n8k8.row.col.f32.tf32.tf32.f32 "
        "{%0,%1,%2,%3}, {%4,%5,%6,%7}, {%8,%9}, {%0,%1,%2,%3};\n"
        : "+f"(d[0]), "+f"(d[1]), "+f"(d[2]), "+f"(d[3])
        : "r"(a[0]), "r"(a[1]), "r"(a[2]), "r"(a[3]), "r"(b[0]), "r"(b[1]));
}

// fp16 mma, fp32 accumulate
__device__ __forceinline__ void mma_f16(float* d, const unsigned* a, const unsigned* b) {
    asm volatile(
        "mma.sync.aligned.m16n8k16.row.col.f32.f16.f16.f32 "
        "{%0,%1,%2,%3}, {%4,%5,%6,%7}, {%8,%9}, {%0,%1,%2,%3};\n"
        : "+f"(d[0]), "+f"(d[1]), "+f"(d[2]), "+f"(d[3])
        : "r"(a[0]), "r"(a[1]), "r"(a[2]), "r"(a[3]), "r"(b[0]), "r"(b[1]));
}

__device__ __forceinline__ void cp16(const void* dst_smem, const void* src) {
    unsigned d = (unsigned)__cvta_generic_to_shared(dst_smem);
    asm volatile("cp.async.cg.shared.global [%0], [%1], 16;\n" :: "r"(d), "l"(src));
}

extern __shared__ char smem_c[];

// ---------------------------------------------------------------------------
// pre-pass kernels
// ---------------------------------------------------------------------------
// fp32 -> fp16 copy; n4 = n/4
__global__ __launch_bounds__(256) void cvt_f2h(
    const float* __restrict__ in, __half* __restrict__ out, int n4)
{
    int i = blockIdx.x * 256 + threadIdx.x;
    if (i < n4) {
        float4 v = ((const float4*)in)[i];
        __half2 h0 = __floats2half2_rn(v.x, v.y);
        __half2 h1 = __floats2half2_rn(v.z, v.w);
        uint2 w;
        w.x = *(unsigned*)&h0;
        w.y = *(unsigned*)&h1;
        ((uint2*)out)[i] = w;
    }
}

// transpose fp32 [R][C] -> fp16 [C][R]; R,C multiples of 32
__global__ __launch_bounds__(256) void transpose_f2h(
    const float* __restrict__ in, __half* __restrict__ out, int R, int C)
{
    __shared__ float t[32][33];
    int bx = blockIdx.x * 32, by = blockIdx.y * 32;
    int x = threadIdx.x, y = threadIdx.y;   // 32 x 8
#pragma unroll
    for (int i = 0; i < 32; i += 8)
        t[y + i][x] = in[(size_t)(by + y + i) * C + bx + x];
    __syncthreads();
#pragma unroll
    for (int i = 0; i < 32; i += 8)
        out[(size_t)(bx + y + i) * R + by + x] = __float2half_rn(t[x][y + i]);
}

// ---------------------------------------------------------------------------
// FP16 tensor-core GEMM, 3-stage cp.async pipeline.
//   C[M,N] = A[M,K] @ Bt[N,K]^T + bias   (A,Bt fp16; accum fp32)
// BM=128 BN=128 BK=32, 256 threads (8 warps, 2m x 4n), warp tile 64x32.
// OUTH: write fp16 (for intermediates); else fp32.
// ---------------------------------------------------------------------------
#define SA 40                               // half stride (conflict-free)
#define TILE_H (128 * SA)                   // halves per tile buffer
#define STAGE_H (2 * TILE_H)                // A+B per stage
#define GEMMH_SMEM_BYTES (3 * STAGE_H * 2)  // 61,440 B

template <bool GELU, bool OUTH>
__global__ __launch_bounds__(256, 2) void gemm_h(
    const __half* __restrict__ A, const __half* __restrict__ Bt,
    const float* __restrict__ bias, void* __restrict__ Cout,
    int M, int N, int K)
{
    __half* Asm = (__half*)smem_c;                  // 3 * TILE_H
    __half* Bsm = (__half*)smem_c + 3 * TILE_H;     // 3 * TILE_H

    const int tid  = threadIdx.x;
    const int warp = tid >> 5, lane = tid & 31;
    const int gid  = lane >> 2, tig = lane & 3;
    const int wm   = (warp & 1) * 64;
    const int wn   = (warp >> 1) * 32;
    const int bm   = blockIdx.y * 128;
    const int bn   = blockIdx.x * 128;

    auto load_stage = [&](int k0, int s) {
        __half* a = Asm + s * TILE_H;
        __half* b = Bsm + s * TILE_H;
#pragma unroll
        for (int it = 0; it < 2; it++) {
            int id = tid + 256 * it;          // 0..511
            int r = id >> 2, q = id & 3;      // row, 8-half chunk
            cp16(a + r * SA + q * 8, A + (size_t)(bm + r) * K + k0 + q * 8);
        }
#pragma unroll
        for (int it = 0; it < 2; it++) {
            int id = tid + 256 * it;
            int r = id >> 2, q = id & 3;
            cp16(b + r * SA + q * 8, Bt + (size_t)(bn + r) * K + k0 + q * 8);
        }
        asm volatile("cp.async.commit_group;\n");
    };

    float d[4][4][4];
#pragma unroll
    for (int i = 0; i < 4; i++)
#pragma unroll
        for (int j = 0; j < 4; j++)
#pragma unroll
            for (int r = 0; r < 4; r++) d[i][j][r] = 0.0f;

    const int T = K >> 5;
    load_stage(0, 0);
    if (T > 1) load_stage(32, 1);

    for (int i = 0; i < T; i++) {
        if (i + 1 < T) {
            asm volatile("cp.async.wait_group 1;\n");
        } else {
            asm volatile("cp.async.wait_group 0;\n");
        }
        __syncthreads();

        const __half* a = Asm + (i % 3) * TILE_H;
        const __half* b = Bsm + (i % 3) * TILE_H;

#pragma unroll
        for (int ks = 0; ks < 2; ks++) {
            const int k16 = ks * 16;
            unsigned af[4][4], bf[4][2];
#pragma unroll
            for (int ii = 0; ii < 4; ii++) {
                int m = wm + 16 * ii + gid;
                const __half* ap = a + m * SA + k16 + 2 * tig;
                af[ii][0] = *(const unsigned*)ap;
                af[ii][1] = *(const unsigned*)(ap + 8 * SA);
                af[ii][2] = *(const unsigned*)(ap + 8);
                af[ii][3] = *(const unsigned*)(ap + 8 * SA + 8);
            }
#pragma unroll
            for (int j = 0; j < 4; j++) {
                int n = wn + 8 * j + gid;
                const __half* bp = b + n * SA + k16 + 2 * tig;
                bf[j][0] = *(const unsigned*)bp;
                bf[j][1] = *(const unsigned*)(bp + 8);
            }
#pragma unroll
            for (int ii = 0; ii < 4; ii++)
#pragma unroll
                for (int j = 0; j < 4; j++)
                    mma_f16(d[ii][j], af[ii], bf[j]);
        }

        if (i + 2 < T) load_stage((i + 2) * 32, (i + 2) % 3);
    }

#pragma unroll
    for (int i = 0; i < 4; i++) {
        int row = bm + wm + 16 * i + gid;
#pragma unroll
        for (int j = 0; j < 4; j++) {
            int col = bn + wn + 8 * j + 2 * tig;
            float bx = bias[col], by = bias[col + 1];
            float r0 = d[i][j][0] + bx, r1 = d[i][j][1] + by;
            float r2 = d[i][j][2] + bx, r3 = d[i][j][3] + by;
            if (GELU) {
                r0 = gelu_f(r0); r1 = gelu_f(r1);
                r2 = gelu_f(r2); r3 = gelu_f(r3);
            }
            if (OUTH) {
                __half* C = (__half*)Cout;
                *(__half2*)(C + (size_t)row * N + col)       = __floats2half2_rn(r0, r1);
                *(__half2*)(C + (size_t)(row + 8) * N + col) = __floats2half2_rn(r2, r3);
            } else {
                float* C = (float*)Cout;
                *(float2*)(C + (size_t)row * N + col)       = make_float2(r0, r1);
                *(float2*)(C + (size_t)(row + 8) * N + col) = make_float2(r2, r3);
            }
        }
    }
}

// ---------------------------------------------------------------------------
// GEMM2 split-K fp16: part[ks][NR,64] = h[:,ks*512:+512] @ enc_w2-slice
// A = h fp16 [m][DI]; Bt = w2t fp16 [64][DI]. BM=128 BN=64 BK=32,
// 8 warps (4m x 2n), warp tile 32x32. fp32 partials out.
// ---------------------------------------------------------------------------
__global__ __launch_bounds__(256, 2) void gemm2_h(
    const __half* __restrict__ A, const __half* __restrict__ Bt,
    float* __restrict__ part)
{
    __shared__ __half As[128 * SA];
    __shared__ __half Bs[64 * SA];

    const int tid  = threadIdx.x;
    const int warp = tid >> 5, lane = tid & 31;
    const int gid  = lane >> 2, tig = lane & 3;
    const int wm   = (warp & 3) * 32;
    const int wn   = (warp >> 2) * 32;
    const int bm   = blockIdx.y * 128;
    const int kbeg = blockIdx.x * (DI / KSPLIT);

    float d[2][4][4];
#pragma unroll
    for (int i = 0; i < 2; i++)
#pragma unroll
        for (int j = 0; j < 4; j++)
#pragma unroll
            for (int r = 0; r < 4; r++) d[i][j][r] = 0.0f;

    for (int kk = 0; kk < DI / KSPLIT; kk += 32) {
        const int k0 = kbeg + kk;
#pragma unroll
        for (int it = 0; it < 2; it++) {
            int id = tid + 256 * it;
            int r = id >> 2, q = id & 3;
            cp16(As + r * SA + q * 8, A + (size_t)(bm + r) * DI + k0 + q * 8);
        }
        {
            int r = tid >> 2, q = tid & 3;   // 64 rows x 4 chunks = 256
            cp16(Bs + r * SA + q * 8, Bt + (size_t)r * DI + k0 + q * 8);
        }
        asm volatile("cp.async.commit_group;\n");
        asm volatile("cp.async.wait_group 0;\n");
        __syncthreads();

#pragma unroll
        for (int ks = 0; ks < 2; ks++) {
            const int k16 = ks * 16;
            unsigned a[2][4], bf[4][2];
#pragma unroll
            for (int i = 0; i < 2; i++) {
                int m = wm + 16 * i + gid;
                const __half* ap = As + m * SA + k16 + 2 * tig;
                a[i][0] = *(const unsigned*)ap;
                a[i][1] = *(const unsigned*)(ap + 8 * SA);
                a[i][2] = *(const unsigned*)(ap + 8);
                a[i][3] = *(const unsigned*)(ap + 8 * SA + 8);
            }
#pragma unroll
            for (int j = 0; j < 4; j++) {
                int n = wn + 8 * j + gid;
                const __half* bp = Bs + n * SA + k16 + 2 * tig;
                bf[j][0] = *(const unsigned*)bp;
                bf[j][1] = *(const unsigned*)(bp + 8);
            }
#pragma unroll
            for (int i = 0; i < 2; i++)
#pragma unroll
                for (int j = 0; j < 4; j++)
                    mma_f16(d[i][j], a[i], bf[j]);
        }
        __syncthreads();
    }

    float* op = part + (size_t)blockIdx.x * NR * DL;
#pragma unroll
    for (int i = 0; i < 2; i++) {
        int row = bm + wm + 16 * i + gid;
#pragma unroll
        for (int j = 0; j < 4; j++) {
            int col = wn + 8 * j + 2 * tig;
            *(float2*)(op + (size_t)row * DL + col)       = make_float2(d[i][j][0], d[i][j][1]);
            *(float2*)(op + (size_t)(row + 8) * DL + col) = make_float2(d[i][j][2], d[i][j][3]);
        }
    }
}

// Sum split-K partials + bias, LayerNorm over 64 cols. One warp per row.
__global__ __launch_bounds__(256) void ln64_k(
    const float* __restrict__ part, const float* __restrict__ bias,
    const float* __restrict__ lg, const float* __restrict__ lb,
    float* __restrict__ out, __half* __restrict__ out_h)
{
    int row  = blockIdx.x * 8 + (threadIdx.x >> 5);
    int lane = threadIdx.x & 31;
    int c0 = lane, c1 = lane + 32;
    float v0 = bias[c0], v1 = bias[c1];
#pragma unroll
    for (int s = 0; s < KSPLIT; s++) {
        const float* p = part + ((size_t)s * NR + row) * DL;
        v0 += p[c0];
        v1 += p[c1];
    }
    float sm = v0 + v1;
#pragma unroll
    for (int o = 16; o; o >>= 1) sm += __shfl_xor_sync(0xffffffffu, sm, o);
    float mu = sm * (1.0f / 64.0f);
    float d0 = v0 - mu, d1 = v1 - mu;
    float sv = fmaf(d0, d0, d1 * d1);
#pragma unroll
    for (int o = 16; o; o >>= 1) sv += __shfl_xor_sync(0xffffffffu, sv, o);
    float rs = rsqrtf(sv * (1.0f / 64.0f) + 1e-9f);
    float r0 = d0 * rs * lg[c0] + lb[c0];
    float r1 = d1 * rs * lg[c1] + lb[c1];
    float* op = out + (size_t)row * DL;
    op[c0] = r0;
    op[c1] = r1;
    __half* oh = out_h + (size_t)row * DL;   // fp16 copy for GEMM3's A
    oh[c0] = __float2half_rn(r0);
    oh[c1] = __float2half_rn(r1);
}

// ---------------------------------------------------------------------------
// In-place LayerNorm over D=1024, one block per row.
// ---------------------------------------------------------------------------
__device__ __forceinline__ float block_sum_256(float v, float* red) {
#pragma unroll
    for (int o = 16; o; o >>= 1) v += __shfl_xor_sync(0xffffffffu, v, o);
    if ((threadIdx.x & 31) == 0) red[threadIdx.x >> 5] = v;
    __syncthreads();
    float t = 0.0f;
#pragma unroll
    for (int i = 0; i < 8; i++) t += red[i];
    __syncthreads();
    return t;
}

__global__ __launch_bounds__(256) void ln1024(
    float* __restrict__ x, const float* __restrict__ lg, const float* __restrict__ lb)
{
    __shared__ float red[8];
    float* p = x + (size_t)blockIdx.x * DD;
    const int tid = threadIdx.x;
    float v[4];
    float s = 0.0f;
#pragma unroll
    for (int i = 0; i < 4; i++) { v[i] = p[tid + i * 256]; s += v[i]; }
    float mu = block_sum_256(s, red) * (1.0f / 1024.0f);
    float s2 = 0.0f;
#pragma unroll
    for (int i = 0; i < 4; i++) {
        float dd = v[i] - mu;
        s2 = fmaf(dd, dd, s2);
    }
    float var = block_sum_256(s2, red) * (1.0f / 1024.0f);
    float rs = rsqrtf(var + 1e-9f);
#pragma unroll
    for (int i = 0; i < 4; i++) {
        int col = tid + i * 256;
        p[col] = (v[i] - mu) * rs * lg[col] + lb[col];
    }
}

// ---------------------------------------------------------------------------
// Per-row squared norms for DL=64 vectors.
// ---------------------------------------------------------------------------
__global__ __launch_bounds__(256) void rowsq(
    const float* __restrict__ X, float* __restrict__ o)
{
    int row = blockIdx.x * 8 + (threadIdx.x >> 5);
    int lane = threadIdx.x & 31;
    const float* p = X + (size_t)row * DL;
    float a = p[lane], b = p[lane + 32];
    float s = fmaf(a, a, b * b);
#pragma unroll
    for (int off = 16; off; off >>= 1) s += __shfl_xor_sync(0xffffffffu, s, off);
    if (lane == 0) o[row] = s;
}

// ---------------------------------------------------------------------------
// Tensor-core RBF kernel-mean tile, 128x128 per block (hi/lo tf32 split).
// fp32-accurate on purpose: the loss sits on a Kxx+Kyy-2Kxy cancellation.
// ---------------------------------------------------------------------------
#define MMD_STRIDE 68
#define MMD_TILE_ELEMS (128 * MMD_STRIDE)
#define MMD_SMEM_BYTES (4 * MMD_TILE_ELEMS * 4)

__global__ __launch_bounds__(256) void mmd_tc(
    const float* __restrict__ X, const float* __restrict__ Y,
    const float* __restrict__ x2, const float* __restrict__ y2,
    double* __restrict__ acc, int sym)
{
    const int bi = blockIdx.y, bj = blockIdx.x;
    if (sym && bi > bj) return;

    float* smem = (float*)smem_c;
    float* Xh = smem;
    float* Xl = smem + MMD_TILE_ELEMS;
    float* Yh = smem + 2 * MMD_TILE_ELEMS;
    float* Yl = smem + 3 * MMD_TILE_ELEMS;

    const int tid  = threadIdx.x;
    const int warp = tid >> 5, lane = tid & 31;
    const int gid  = lane >> 2, tig = lane & 3;
    const int wm   = (warp & 1) * 64;
    const int wn   = (warp >> 1) * 32;
    const int i0 = bi * 128, j0 = bj * 128;

#pragma unroll
    for (int it = 0; it < 8; it++) {
        int id = tid + 256 * it;
        int r = id >> 4, c = (id & 15) << 2;
        float4 v = *(const float4*)(X + (size_t)(i0 + r) * DL + c);
        float4 h, l;
        h.x = tf32r(v.x); l.x = tf32r(v.x - h.x);
        h.y = tf32r(v.y); l.y = tf32r(v.y - h.y);
        h.z = tf32r(v.z); l.z = tf32r(v.z - h.z);
        h.w = tf32r(v.w); l.w = tf32r(v.w - h.w);
        *(float4*)&Xh[r * MMD_STRIDE + c] = h;
        *(float4*)&Xl[r * MMD_STRIDE + c] = l;
    }
#pragma unroll
    for (int it = 0; it < 8; it++) {
        int id = tid + 256 * it;
        int r = id >> 4, c = (id & 15) << 2;
        float4 v = *(const float4*)(Y + (size_t)(j0 + r) * DL + c);
        float4 h, l;
        h.x = tf32r(v.x); l.x = tf32r(v.x - h.x);
        h.y = tf32r(v.y); l.y = tf32r(v.y - h.y);
        h.z = tf32r(v.z); l.z = tf32r(v.z - h.z);
        h.w = tf32r(v.w); l.w = tf32r(v.w - h.w);
        *(float4*)&Yh[r * MMD_STRIDE + c] = h;
        *(float4*)&Yl[r * MMD_STRIDE + c] = l;
    }
    __syncthreads();

    float d[4][4][4];
#pragma unroll
    for (int i = 0; i < 4; i++)
#pragma unroll
        for (int j = 0; j < 4; j++)
#pragma unroll
            for (int r = 0; r < 4; r++) d[i][j][r] = 0.0f;

#pragma unroll
    for (int ks = 0; ks < 8; ks++) {
        const int k8 = ks * 8;
        unsigned ah[4][4], al[4][4], bh[4][2], bl[4][2];
#pragma unroll
        for (int ii = 0; ii < 4; ii++) {
            int m = wm + 16 * ii + gid;
            ah[ii][0] = __float_as_uint(Xh[m * MMD_STRIDE + k8 + tig]);
            ah[ii][1] = __float_as_uint(Xh[(m + 8) * MMD_STRIDE + k8 + tig]);
            ah[ii][2] = __float_as_uint(Xh[m * MMD_STRIDE + k8 + tig + 4]);
            ah[ii][3] = __float_as_uint(Xh[(m + 8) * MMD_STRIDE + k8 + tig + 4]);
            al[ii][0] = __float_as_uint(Xl[m * MMD_STRIDE + k8 + tig]);
            al[ii][1] = __float_as_uint(Xl[(m + 8) * MMD_STRIDE + k8 + tig]);
            al[ii][2] = __float_as_uint(Xl[m * MMD_STRIDE + k8 + tig + 4]);
            al[ii][3] = __float_as_uint(Xl[(m + 8) * MMD_STRIDE + k8 + tig + 4]);
        }
#pragma unroll
        for (int j = 0; j < 4; j++) {
            int n = wn + 8 * j + gid;
            bh[j][0] = __float_as_uint(Yh[n * MMD_STRIDE + k8 + tig]);
            bh[j][1] = __float_as_uint(Yh[n * MMD_STRIDE + k8 + tig + 4]);
            bl[j][0] = __float_as_uint(Yl[n * MMD_STRIDE + k8 + tig]);
            bl[j][1] = __float_as_uint(Yl[n * MMD_STRIDE + k8 + tig + 4]);
        }
#pragma unroll
        for (int ii = 0; ii < 4; ii++)
#pragma unroll
            for (int j = 0; j < 4; j++) {
                mma_tf32(d[ii][j], ah[ii], bh[j]);
                mma_tf32(d[ii][j], ah[ii], bl[j]);
                mma_tf32(d[ii][j], al[ii], bh[j]);
            }
    }

    float xiA[4], xiB[4], yjA[4], yjB[4];
#pragma unroll
    for (int i = 0; i < 4; i++) {
        int row = i0 + wm + 16 * i + gid;
        xiA[i] = x2[row];
        xiB[i] = x2[row + 8];
    }
#pragma unroll
    for (int j = 0; j < 4; j++) {
        int col = j0 + wn + 8 * j + 2 * tig;
        yjA[j] = y2[col];
        yjB[j] = y2[col + 1];
    }

    auto expm = [](float t) {
        float e = fmaf(t, -1.0f / 720.0f, 1.0f / 120.0f);
        e = fmaf(t, e, -1.0f / 24.0f);
        e = fmaf(t, e, 1.0f / 6.0f);
        e = fmaf(t, e, -0.5f);
        e = fmaf(t, e, 1.0f);
        e = fmaf(-t, e, 1.0f);
        if (t > 0.5f) e = __expf(-t);
        return e;
    };

    float lsum = 0.0f;
#pragma unroll
    for (int i = 0; i < 4; i++)
#pragma unroll
        for (int j = 0; j < 4; j++) {
            float s0 = xiA[i] + yjA[j] - 2.0f * d[i][j][0];
            float s1 = xiA[i] + yjB[j] - 2.0f * d[i][j][1];
            float s2 = xiB[i] + yjA[j] - 2.0f * d[i][j][2];
            float s3 = xiB[i] + yjB[j] - 2.0f * d[i][j][3];
            lsum += expm(s0 * (1.0f / 4096.0f));
            lsum += expm(s1 * (1.0f / 4096.0f));
            lsum += expm(s2 * (1.0f / 4096.0f));
            lsum += expm(s3 * (1.0f / 4096.0f));
        }

    if (sym && bi != bj) lsum *= 2.0f;

#pragma unroll
    for (int off = 16; off; off >>= 1)
        lsum += __shfl_xor_sync(0xffffffffu, lsum, off);

    __shared__ float ws[8];
    if ((tid & 31) == 0) ws[tid >> 5] = lsum;
    __syncthreads();
    if (tid == 0) {
        double t = 0.0;
#pragma unroll
        for (int w = 0; w < 8; w++) t += (double)ws[w];
        atomicAdd(acc, t);
    }
}

__global__ void zero_acc_k() {
    if (threadIdx.x < 3) g_acc[threadIdx.x] = 0.0;
}

__global__ void finalize_loss(float* __restrict__ out) {
    const double inv = 1.0 / (4096.0 * 4096.0);
    double mmd = (g_acc[0] + g_acc[1] - 2.0 * g_acc[2]) * inv;
    out[0] = (float)(mmd * 64.0);
}

// ---------------------------------------------------------------------------
extern "C" void kernel_launch(void* const* d_in, const int* in_sizes, int n_in,
                              void* d_out, int out_size)
{
    const float* hidden = (const float*)d_in[0];
    const float* true_s = (const float*)d_in[1];
    const float* enc_w1 = (const float*)d_in[2];
    const float* enc_b1 = (const float*)d_in[3];
    const float* enc_w2 = (const float*)d_in[4];
    const float* enc_b2 = (const float*)d_in[5];
    const float* enc_g  = (const float*)d_in[6];
    const float* enc_lb = (const float*)d_in[7];
    const float* dec_w1 = (const float*)d_in[8];
    const float* dec_b1 = (const float*)d_in[9];
    const float* dec_w2 = (const float*)d_in[10];
    const float* dec_b2 = (const float*)d_in[11];
    const float* dec_g  = (const float*)d_in[12];
    const float* dec_lb = (const float*)d_in[13];

    float* recon  = (float*)d_out;
    float* latent = recon + (size_t)NR * DD;
    float* loss   = latent + (size_t)NR * DL;

    __half* hh;   cudaGetSymbolAddress((void**)&hh,   g_hh);
    float*  part; cudaGetSymbolAddress((void**)&part, g_part);
    __half* hidh; cudaGetSymbolAddress((void**)&hidh, g_hidh);
    __half* w1t;  cudaGetSymbolAddress((void**)&w1t,  g_w1t);
    __half* w2t;  cudaGetSymbolAddress((void**)&w2t,  g_w2t);
    __half* d1t;  cudaGetSymbolAddress((void**)&d1t,  g_d1t);
    __half* d2t;  cudaGetSymbolAddress((void**)&d2t,  g_d2t);
    __half* lath; cudaGetSymbolAddress((void**)&lath, g_lath);
    float*  x2;   cudaGetSymbolAddress((void**)&x2,   g_x2);
    float*  y2;   cudaGetSymbolAddress((void**)&y2,   g_y2);
    double* acc;  cudaGetSymbolAddress((void**)&acc,  g_acc);

    static cudaStream_t s1 = nullptr, s2 = nullptr;
    static cudaEvent_t e0, e_lat, e_w, e_end;
    if (!s1) {
        cudaStreamCreateWithFlags(&s1, cudaStreamNonBlocking);
        cudaStreamCreateWithFlags(&s2, cudaStreamNonBlocking);
        cudaEventCreateWithFlags(&e0,    cudaEventDisableTiming);
        cudaEventCreateWithFlags(&e_lat, cudaEventDisableTiming);
        cudaEventCreateWithFlags(&e_w,   cudaEventDisableTiming);
        cudaEventCreateWithFlags(&e_end, cudaEventDisableTiming);
        cudaFuncSetAttribute(gemm_h<true, true>,
                             cudaFuncAttributeMaxDynamicSharedMemorySize,
                             GEMMH_SMEM_BYTES);
        cudaFuncSetAttribute(gemm_h<false, false>,
                             cudaFuncAttributeMaxDynamicSharedMemorySize,
                             GEMMH_SMEM_BYTES);
        cudaFuncSetAttribute(mmd_tc,
                             cudaFuncAttributeMaxDynamicSharedMemorySize,
                             MMD_SMEM_BYTES);
    }

    // root (captured origin stream)
    zero_acc_k<<<1, 32>>>();
    cudaEventRecord(e0, 0);

    // ---- branch s1: input-only MMD work (overlaps encoder GEMM1) ----
    cudaStreamWaitEvent(s1, e0, 0);
    rowsq<<<NR / 8, 256, 0, s1>>>(true_s, x2);
    mmd_tc<<<dim3(32, 32), 256, MMD_SMEM_BYTES, s1>>>(true_s, true_s, x2, x2,
                                                      acc + 0, 1);

    // ---- branch s2: decoder/enc2 weight transposes (overlap GEMM1) ----
    cudaStreamWaitEvent(s2, e0, 0);
    transpose_f2h<<<dim3(DI / 32, DL / 32), dim3(32, 8), 0, s2>>>(dec_w1, d1t, DL, DI);
    transpose_f2h<<<dim3(DD / 32, DI / 32), dim3(32, 8), 0, s2>>>(dec_w2, d2t, DI, DD);
    transpose_f2h<<<dim3(DL / 32, DI / 32), dim3(32, 8), 0, s2>>>(enc_w2, w2t, DI, DL);
    cudaEventRecord(e_w, s2);

    // ---- main stream: encoder ----
    cvt_f2h<<<(NR * DD / 4 + 255) / 256, 256>>>(hidden, hidh, NR * DD / 4);
    transpose_f2h<<<dim3(DI / 32, DD / 32), dim3(32, 8)>>>(enc_w1, w1t, DD, DI);
    gemm_h<true, true><<<dim3(DI / 128, NR / 128), 256, GEMMH_SMEM_BYTES>>>(
        hidh, w1t, enc_b1, hh, NR, DI, DD);
    cudaStreamWaitEvent(0, e_w, 0);   // need w2t below
    gemm2_h<<<dim3(KSPLIT, NR / 128), 256>>>(hh, w2t, part);
    ln64_k<<<NR / 8, 256>>>(part, enc_b2, enc_g, enc_lb, latent, lath);
    cudaEventRecord(e_lat, 0);

    // ---- branch s1: latent-dependent MMD (overlaps decoder GEMMs) ----
    cudaStreamWaitEvent(s1, e_lat, 0);
    rowsq<<<NR / 8, 256, 0, s1>>>(latent, y2);
    mmd_tc<<<dim3(32, 32), 256, MMD_SMEM_BYTES, s1>>>(latent, latent, y2, y2,
                                                      acc + 1, 1);
    mmd_tc<<<dim3(32, 32), 256, MMD_SMEM_BYTES, s1>>>(true_s, latent, x2, y2,
                                                      acc + 2, 0);
    finalize_loss<<<1, 1, 0, s1>>>(loss);
    cudaEventRecord(e_end, s1);

    // ---- main stream: decoder ----
    gemm_h<true, true><<<dim3(DI / 128, NR / 128), 256, GEMMH_SMEM_BYTES>>>(
        lath, d1t, dec_b1, hh, NR, DI, DL);
    gemm_h<false, false><<<dim3(DD / 128, NR / 128), 256, GEMMH_SMEM_BYTES>>>(
        hh, d2t, dec_b2, recon, NR, DD, DI);
    ln1024<<<NR, 256>>>(recon, dec_g, dec_lb);

    // join MMD branch before returning
    cudaStreamWaitEvent(0, e_end, 0);
}